// round 3
// baseline (speedup 1.0000x reference)
#include <cuda_runtime.h>
#include <cstdint>
#include <cstddef>

#define DM 1024
#define NH 16
#define DK 64
#define BB 2
#define SSEQ 2048
#define MTOT (BB*SSEQ)     // 4096
#define BH (BB*NH)         // 32

// Scratch (allocation-free rule: __device__ globals). All stored tf32-rounded.
__device__ float g_q[(size_t)BH*SSEQ*DK];      // [B,H,S,dk]   tf32
__device__ float g_k[(size_t)BH*SSEQ*DK];      // [B,H,S,dk]   tf32
__device__ float g_vT[(size_t)BH*DK*SSEQ];     // [B,H,dk,S]   tf32
__device__ float g_attn[(size_t)MTOT*DM];      // merged [B,S,D] fp32

// ---------------------------------------------------------------------------
// TF32 mma.sync helpers
// ---------------------------------------------------------------------------
__device__ __forceinline__ uint32_t f2tf32(float x) {
    uint32_t r;
    asm("cvt.rna.tf32.f32 %0, %1;\n" : "=r"(r) : "f"(x));
    return r;
}
__device__ __forceinline__ uint4 cvt4(float4 v) {
    uint4 r;
    r.x = f2tf32(v.x); r.y = f2tf32(v.y); r.z = f2tf32(v.z); r.w = f2tf32(v.w);
    return r;
}
__device__ __forceinline__ void mma_tf32(float* c, const uint32_t* a, const uint32_t* b) {
    asm volatile(
        "mma.sync.aligned.m16n8k8.row.col.f32.tf32.tf32.f32 "
        "{%0,%1,%2,%3}, {%4,%5,%6,%7}, {%8,%9}, {%0,%1,%2,%3};\n"
        : "+f"(c[0]), "+f"(c[1]), "+f"(c[2]), "+f"(c[3])
        : "r"(a[0]), "r"(a[1]), "r"(a[2]), "r"(a[3]), "r"(b[0]), "r"(b[1]));
}
__device__ __forceinline__ void cp16(uint32_t d, const void* s) {
    asm volatile("cp.async.ca.shared.global [%0], [%1], 16;\n" :: "r"(d), "l"(s));
}
__device__ __forceinline__ void cp_commit() { asm volatile("cp.async.commit_group;\n"); }
template<int N> __device__ __forceinline__ void cp_wait() {
    asm volatile("cp.async.wait_group %0;\n" :: "n"(N));
}

// ---------------------------------------------------------------------------
// Projection GEMM: C[4096,1024] = A[4096,1024] @ W[1024,1024]^T + bias
// mode 0: fp32 out[m][n]; mode 1: tf32 split-heads [bh,s,64]; mode 2: tf32 V^T [bh,64,s]
// ---------------------------------------------------------------------------
__global__ void __launch_bounds__(256) proj_tf32(
    const float* __restrict__ A, const float* __restrict__ W,
    const float* __restrict__ bias, float* __restrict__ out, int mode)
{
    __shared__ uint32_t As[128][20];
    __shared__ uint32_t Bs[128][20];
    const int tid = threadIdx.x;
    const int m0 = blockIdx.y * 128, n0 = blockIdx.x * 128;
    const int lane = tid & 31, warp = tid >> 5;
    const int wm = (warp & 3) * 32, wn = (warp >> 2) * 64;
    const int g = lane >> 2, t = lane & 3;
    const int lr = tid >> 2;
    const int lk = (tid & 3) * 4;

    const float* Ab = A + (size_t)(m0 + lr) * 1024 + lk;
    const float* Wb = W + (size_t)(n0 + lr) * 1024 + lk;

    float4 ra0 = *(const float4*)(Ab);
    float4 ra1 = *(const float4*)(Ab + (size_t)64 * 1024);
    float4 rb0 = *(const float4*)(Wb);
    float4 rb1 = *(const float4*)(Wb + (size_t)64 * 1024);

    float c[2][8][4] = {};

    for (int k0 = 16; k0 <= 1024; k0 += 16) {
        *(uint4*)&As[lr][lk]      = cvt4(ra0);
        *(uint4*)&As[lr + 64][lk] = cvt4(ra1);
        *(uint4*)&Bs[lr][lk]      = cvt4(rb0);
        *(uint4*)&Bs[lr + 64][lk] = cvt4(rb1);
        __syncthreads();
        if (k0 < 1024) {
            ra0 = *(const float4*)(Ab + k0);
            ra1 = *(const float4*)(Ab + (size_t)64 * 1024 + k0);
            rb0 = *(const float4*)(Wb + k0);
            rb1 = *(const float4*)(Wb + (size_t)64 * 1024 + k0);
        }
#pragma unroll
        for (int ks = 0; ks < 2; ks++) {
            const int kb = ks * 8;
            uint32_t af[2][4], bf[8][2];
#pragma unroll
            for (int mi = 0; mi < 2; mi++) {
                const int r = wm + mi * 16 + g;
                af[mi][0] = As[r][kb + t];
                af[mi][1] = As[r + 8][kb + t];
                af[mi][2] = As[r][kb + t + 4];
                af[mi][3] = As[r + 8][kb + t + 4];
            }
#pragma unroll
            for (int ni = 0; ni < 8; ni++) {
                const int cc = wn + ni * 8 + g;
                bf[ni][0] = Bs[cc][kb + t];
                bf[ni][1] = Bs[cc][kb + t + 4];
            }
#pragma unroll
            for (int mi = 0; mi < 2; mi++)
#pragma unroll
                for (int ni = 0; ni < 8; ni++)
                    mma_tf32(c[mi][ni], af[mi], bf[ni]);
        }
        __syncthreads();
    }

#pragma unroll
    for (int mi = 0; mi < 2; mi++) {
#pragma unroll
        for (int rr = 0; rr < 2; rr++) {
            const int m = m0 + wm + mi * 16 + g + rr * 8;
            const int b_ = m >> 11, s = m & 2047;
#pragma unroll
            for (int ni = 0; ni < 8; ni++) {
                const int n = n0 + wn + ni * 8 + 2 * t;
                float v0 = c[mi][ni][rr * 2 + 0] + bias[n];
                float v1 = c[mi][ni][rr * 2 + 1] + bias[n + 1];
                if (mode == 0) {
                    *(float2*)&out[(size_t)m * 1024 + n] = make_float2(v0, v1);
                } else {
                    // round to tf32 once here so downstream kernels can use raw bits
                    v0 = __uint_as_float(f2tf32(v0));
                    v1 = __uint_as_float(f2tf32(v1));
                    const int h = n >> 6, d = n & 63;
                    if (mode == 1) {
                        *(float2*)&out[(((size_t)(b_ * 16 + h) * 2048 + s) << 6) + d] =
                            make_float2(v0, v1);
                    } else {
                        out[((size_t)(b_ * 16 + h) * 64 + d) * 2048 + s] = v0;
                        out[((size_t)(b_ * 16 + h) * 64 + d + 1) * 2048 + s] = v1;
                    }
                }
            }
        }
    }
}

// ---------------------------------------------------------------------------
// Fused attention: scores + softmax (no-max two-pass) + PV.
// CTA = 128 query rows x one (b,h). 8 warps, warp = 16 rows.
// Pass A: stream K chunks (64 keys), QK^T mma, accumulate rowsum of exp.
// Pass B: re-stream K and V, recompute scores, normalize, write P once,
//         run PV mma from per-warp smem tile. O accum in registers.
// ---------------------------------------------------------------------------
#define CK 64
#define NCH (SSEQ/CK)      // 32
#define KW 68              // smem row stride (words) for K/V chunks
#define KBUF_W (CK*KW)     // 4352
#define SM_K0 0
#define SM_K1 KBUF_W
#define SM_V0 (2*KBUF_W)
#define SM_V1 (3*KBUF_W)
#define SM_P  (4*KBUF_W)   // per-warp P tiles
#define PT_W 68
#define FA_SMEM_WORDS (SM_P + 8*16*PT_W)   // 26112
#define FA_SMEM_BYTES (FA_SMEM_WORDS*4)    // 104448

__global__ void __launch_bounds__(256, 2) fused_attn(
    const unsigned char* __restrict__ mask, float* __restrict__ P)
{
    extern __shared__ uint32_t sm[];
    const int tid = threadIdx.x;
    const int lane = tid & 31, warp = tid >> 5;
    const int g = lane >> 2, t = lane & 3;
    const int bh = blockIdx.y;
    const int i0 = blockIdx.x * 128;
    const int b_ = bh >> 4, h = bh & 15;
    const int wm = warp * 16;

    const float* Qg = g_q + (size_t)bh * SSEQ * DK;
    const float* Kg = g_k + (size_t)bh * SSEQ * DK;
    const float* Vg = g_vT + (size_t)bh * DK * SSEQ;
    float* Pg = P + (size_t)bh * SSEQ * SSEQ;
    const unsigned char* mrow0 = mask + ((size_t)b_ * SSEQ + i0 + wm + g) * SSEQ;
    const unsigned char* mrow1 = mrow0 + (size_t)8 * SSEQ;

    const uint32_t sbase = (uint32_t)__cvta_generic_to_shared(sm);

    // ---- staging helpers (cp.async 16B) ----
    auto stageK = [&](int c) {
        const uint32_t dbase = sbase + ((c & 1) ? SM_K1 : SM_K0) * 4;
        const float* src = Kg + (size_t)c * CK * DK;
#pragma unroll
        for (int s = 0; s < 4; s++) {
            const int idx = tid + s * 256;            // 0..1023 slots of 16B
            const int key = idx >> 4, q = idx & 15;
            cp16(dbase + (uint32_t)(key * KW + q * 4) * 4, src + key * DK + q * 4);
        }
    };
    auto stageV = [&](int c) {
        const uint32_t dbase = sbase + ((c & 1) ? SM_V1 : SM_V0) * 4;
#pragma unroll
        for (int s = 0; s < 4; s++) {
            const int idx = tid + s * 256;
            const int d = idx >> 4, q = idx & 15;
            cp16(dbase + (uint32_t)(d * KW + q * 4) * 4,
                 Vg + (size_t)d * SSEQ + c * CK + q * 4);
        }
    };
    // ---- QK^T for this warp's 16 rows x 64 keys of chunk ----
    auto qk = [&](const uint32_t* Kb, float cc[8][4]) {
#pragma unroll
        for (int ks = 0; ks < 8; ks++) {
            const float* qr = Qg + (size_t)(i0 + wm + g) * DK + ks * 8 + t;
            uint32_t a[4];
            a[0] = __float_as_uint(qr[0]);
            a[1] = __float_as_uint(qr[8 * DK]);
            a[2] = __float_as_uint(qr[4]);
            a[3] = __float_as_uint(qr[8 * DK + 4]);
#pragma unroll
            for (int nt = 0; nt < 8; nt++) {
                uint32_t bb[2] = { Kb[(nt * 8 + g) * KW + ks * 8 + t],
                                   Kb[(nt * 8 + g) * KW + ks * 8 + t + 4] };
                mma_tf32(cc[nt], a, bb);
            }
        }
    };

    // ================= PASS A: row sums =================
    float l0 = 0.f, l1 = 0.f;
    stageK(0); cp_commit();
    for (int c = 0; c < NCH; c++) {
        if (c + 1 < NCH) { stageK(c + 1); cp_commit(); cp_wait<1>(); }
        else             { cp_wait<0>(); }
        __syncthreads();
        const uint32_t* Kb = sm + ((c & 1) ? SM_K1 : SM_K0);
        float cc[8][4] = {};
        qk(Kb, cc);
        const int jc = c * CK;
#pragma unroll
        for (int nt = 0; nt < 8; nt++) {
            const uchar2 m0 = *(const uchar2*)(mrow0 + jc + nt * 8 + 2 * t);
            const uchar2 m1 = *(const uchar2*)(mrow1 + jc + nt * 8 + 2 * t);
            l0 += (m0.x ? 0.f : __expf(cc[nt][0] * 0.125f));
            l0 += (m0.y ? 0.f : __expf(cc[nt][1] * 0.125f));
            l1 += (m1.x ? 0.f : __expf(cc[nt][2] * 0.125f));
            l1 += (m1.y ? 0.f : __expf(cc[nt][3] * 0.125f));
        }
        __syncthreads();
    }
    l0 += __shfl_xor_sync(0xffffffffu, l0, 1);
    l0 += __shfl_xor_sync(0xffffffffu, l0, 2);
    l1 += __shfl_xor_sync(0xffffffffu, l1, 1);
    l1 += __shfl_xor_sync(0xffffffffu, l1, 2);
    const float inv0 = 1.f / l0, inv1 = 1.f / l1;

    // ================= PASS B: normalize + write P + PV =================
    float oacc[8][4] = {};
    float* Pt = (float*)(sm + SM_P) + warp * 16 * PT_W;

    stageK(0); stageV(0); cp_commit();
    for (int c = 0; c < NCH; c++) {
        if (c + 1 < NCH) { stageK(c + 1); stageV(c + 1); cp_commit(); cp_wait<1>(); }
        else             { cp_wait<0>(); }
        __syncthreads();
        const uint32_t* Kb = sm + ((c & 1) ? SM_K1 : SM_K0);
        const uint32_t* Vb = sm + ((c & 1) ? SM_V1 : SM_V0);
        float cc[8][4] = {};
        qk(Kb, cc);
        const int jc = c * CK;
#pragma unroll
        for (int nt = 0; nt < 8; nt++) {
            const uchar2 m0 = *(const uchar2*)(mrow0 + jc + nt * 8 + 2 * t);
            const uchar2 m1 = *(const uchar2*)(mrow1 + jc + nt * 8 + 2 * t);
            const float p00 = m0.x ? 0.f : __expf(cc[nt][0] * 0.125f) * inv0;
            const float p01 = m0.y ? 0.f : __expf(cc[nt][1] * 0.125f) * inv0;
            const float p10 = m1.x ? 0.f : __expf(cc[nt][2] * 0.125f) * inv1;
            const float p11 = m1.y ? 0.f : __expf(cc[nt][3] * 0.125f) * inv1;
            *(float2*)&Pt[g * PT_W + nt * 8 + 2 * t]       = make_float2(p00, p01);
            *(float2*)&Pt[(g + 8) * PT_W + nt * 8 + 2 * t] = make_float2(p10, p11);
        }
        __syncwarp();
        // coalesced store of this warp's 16x64 P tile
#pragma unroll
        for (int r = 0; r < 16; r++) {
            const float2 v = *(const float2*)&Pt[r * PT_W + lane * 2];
            *(float2*)&Pg[(size_t)(i0 + wm + r) * SSEQ + jc + lane * 2] = v;
        }
        // PV: O += P_tile @ V_chunk
#pragma unroll
        for (int ks = 0; ks < 8; ks++) {
            uint32_t a[4];
            a[0] = f2tf32(Pt[g * PT_W + ks * 8 + t]);
            a[1] = f2tf32(Pt[(g + 8) * PT_W + ks * 8 + t]);
            a[2] = f2tf32(Pt[g * PT_W + ks * 8 + t + 4]);
            a[3] = f2tf32(Pt[(g + 8) * PT_W + ks * 8 + t + 4]);
#pragma unroll
            for (int nt = 0; nt < 8; nt++) {
                uint32_t bb[2] = { Vb[(nt * 8 + g) * KW + ks * 8 + t],
                                   Vb[(nt * 8 + g) * KW + ks * 8 + t + 4] };
                mma_tf32(oacc[nt], a, bb);
            }
        }
        __syncwarp();
        __syncthreads();
    }

    // epilogue: write merged attn [B,S,H*64]
#pragma unroll
    for (int nt = 0; nt < 8; nt++) {
        const int d = h * 64 + nt * 8 + 2 * t;
        *(float2*)&g_attn[(size_t)(b_ * SSEQ + i0 + wm + g) * DM + d] =
            make_float2(oacc[nt][0], oacc[nt][1]);
        *(float2*)&g_attn[(size_t)(b_ * SSEQ + i0 + wm + g + 8) * DM + d] =
            make_float2(oacc[nt][2], oacc[nt][3]);
    }
}

// ---------------------------------------------------------------------------
extern "C" void kernel_launch(void* const* d_in, const int* in_sizes, int n_in,
                              void* d_out, int out_size)
{
    const float* Q   = (const float*)d_in[0];
    const float* K   = (const float*)d_in[1];
    const float* V   = (const float*)d_in[2];
    const unsigned char* mask = (const unsigned char*)d_in[3];
    const float* WQw = (const float*)d_in[4];
    const float* WQb = (const float*)d_in[5];
    const float* WKw = (const float*)d_in[6];
    const float* WKb = (const float*)d_in[7];
    const float* WVw = (const float*)d_in[8];
    const float* WVb = (const float*)d_in[9];
    const float* Wow = (const float*)d_in[10];
    const float* Wob = (const float*)d_in[11];

    float* out   = (float*)d_out;                       // [B,S,D]
    float* attnw = out + (size_t)MTOT * DM;             // [B,H,S,S]

    float *pq, *pk, *pv, *pa;
    cudaGetSymbolAddress((void**)&pq, g_q);
    cudaGetSymbolAddress((void**)&pk, g_k);
    cudaGetSymbolAddress((void**)&pv, g_vT);
    cudaGetSymbolAddress((void**)&pa, g_attn);

    cudaFuncSetAttribute(fused_attn, cudaFuncAttributeMaxDynamicSharedMemorySize,
                         FA_SMEM_BYTES);

    proj_tf32<<<dim3(8, 32), 256>>>(Q, WQw, WQb, pq, 1);
    proj_tf32<<<dim3(8, 32), 256>>>(K, WKw, WKb, pk, 1);
    proj_tf32<<<dim3(8, 32), 256>>>(V, WVw, WVb, pv, 2);

    fused_attn<<<dim3(16, 32), 256, FA_SMEM_BYTES>>>(mask, attnw);

    proj_tf32<<<dim3(8, 32), 256>>>(pa, Wow, Wob, out, 0);
}

// round 4
// speedup vs baseline: 1.3253x; 1.3253x over previous
#include <cuda_runtime.h>
#include <cstdint>
#include <cstddef>

#define DM 1024
#define NH 16
#define DK 64
#define BB 2
#define SSEQ 2048
#define MTOT (BB*SSEQ)     // 4096
#define BH (BB*NH)         // 32

// Scratch (__device__ globals; allocation-free rule)
__device__ float g_q[(size_t)BH*SSEQ*DK];        // [B,H,S,dk]   tf32
__device__ float g_k[(size_t)BH*SSEQ*DK];        // [B,H,S,dk]   tf32
__device__ float g_vT[(size_t)BH*DK*SSEQ];       // [B,H,dk,S]   tf32
__device__ float g_attn[(size_t)MTOT*DM];        // merged [B,S,D] fp32
__device__ uint32_t g_mbits[(size_t)BB*SSEQ*(SSEQ/32)];   // 1MB bitmask

// ---------------------------------------------------------------------------
__device__ __forceinline__ uint32_t f2tf32(float x) {
    uint32_t r;
    asm("cvt.rna.tf32.f32 %0, %1;\n" : "=r"(r) : "f"(x));
    return r;
}
__device__ __forceinline__ uint4 cvt4(float4 v) {
    uint4 r;
    r.x = f2tf32(v.x); r.y = f2tf32(v.y); r.z = f2tf32(v.z); r.w = f2tf32(v.w);
    return r;
}
__device__ __forceinline__ void mma_tf32(float* c, const uint32_t* a, const uint32_t* b) {
    asm volatile(
        "mma.sync.aligned.m16n8k8.row.col.f32.tf32.tf32.f32 "
        "{%0,%1,%2,%3}, {%4,%5,%6,%7}, {%8,%9}, {%0,%1,%2,%3};\n"
        : "+f"(c[0]), "+f"(c[1]), "+f"(c[2]), "+f"(c[3])
        : "r"(a[0]), "r"(a[1]), "r"(a[2]), "r"(a[3]), "r"(b[0]), "r"(b[1]));
}
__device__ __forceinline__ void cp16(uint32_t d, const void* s) {
    asm volatile("cp.async.ca.shared.global [%0], [%1], 16;\n" :: "r"(d), "l"(s));
}
__device__ __forceinline__ void cp_commit() { asm volatile("cp.async.commit_group;\n"); }
template<int N> __device__ __forceinline__ void cp_wait() {
    asm volatile("cp.async.wait_group %0;\n" :: "n"(N));
}

// ---------------------------------------------------------------------------
// mask -> bitmask  (bit j of word w = mask[... w*32+j])
// ---------------------------------------------------------------------------
__global__ void maskbits_kernel(const unsigned char* __restrict__ mask)
{
    const int idx = blockIdx.x * 256 + threadIdx.x;          // word index
    const uint32_t* src = (const uint32_t*)(mask + (size_t)idx * 32);
    uint32_t w = 0;
#pragma unroll
    for (int q = 0; q < 8; q++) {
        const uint32_t v = src[q];
        if (v & 0x000000ffu) w |= 1u << (q * 4 + 0);
        if (v & 0x0000ff00u) w |= 1u << (q * 4 + 1);
        if (v & 0x00ff0000u) w |= 1u << (q * 4 + 2);
        if (v & 0xff000000u) w |= 1u << (q * 4 + 3);
    }
    g_mbits[idx] = w;
}

// ---------------------------------------------------------------------------
// Projection GEMM (unchanged from R3)
// ---------------------------------------------------------------------------
__global__ void __launch_bounds__(256) proj_tf32(
    const float* __restrict__ A, const float* __restrict__ W,
    const float* __restrict__ bias, float* __restrict__ out, int mode)
{
    __shared__ uint32_t As[128][20];
    __shared__ uint32_t Bs[128][20];
    const int tid = threadIdx.x;
    const int m0 = blockIdx.y * 128, n0 = blockIdx.x * 128;
    const int lane = tid & 31, warp = tid >> 5;
    const int wm = (warp & 3) * 32, wn = (warp >> 2) * 64;
    const int g = lane >> 2, t = lane & 3;
    const int lr = tid >> 2;
    const int lk = (tid & 3) * 4;

    const float* Ab = A + (size_t)(m0 + lr) * 1024 + lk;
    const float* Wb = W + (size_t)(n0 + lr) * 1024 + lk;

    float4 ra0 = *(const float4*)(Ab);
    float4 ra1 = *(const float4*)(Ab + (size_t)64 * 1024);
    float4 rb0 = *(const float4*)(Wb);
    float4 rb1 = *(const float4*)(Wb + (size_t)64 * 1024);

    float c[2][8][4] = {};

    for (int k0 = 16; k0 <= 1024; k0 += 16) {
        *(uint4*)&As[lr][lk]      = cvt4(ra0);
        *(uint4*)&As[lr + 64][lk] = cvt4(ra1);
        *(uint4*)&Bs[lr][lk]      = cvt4(rb0);
        *(uint4*)&Bs[lr + 64][lk] = cvt4(rb1);
        __syncthreads();
        if (k0 < 1024) {
            ra0 = *(const float4*)(Ab + k0);
            ra1 = *(const float4*)(Ab + (size_t)64 * 1024 + k0);
            rb0 = *(const float4*)(Wb + k0);
            rb1 = *(const float4*)(Wb + (size_t)64 * 1024 + k0);
        }
#pragma unroll
        for (int ks = 0; ks < 2; ks++) {
            const int kb = ks * 8;
            uint32_t af[2][4], bf[8][2];
#pragma unroll
            for (int mi = 0; mi < 2; mi++) {
                const int r = wm + mi * 16 + g;
                af[mi][0] = As[r][kb + t];
                af[mi][1] = As[r + 8][kb + t];
                af[mi][2] = As[r][kb + t + 4];
                af[mi][3] = As[r + 8][kb + t + 4];
            }
#pragma unroll
            for (int ni = 0; ni < 8; ni++) {
                const int cc = wn + ni * 8 + g;
                bf[ni][0] = Bs[cc][kb + t];
                bf[ni][1] = Bs[cc][kb + t + 4];
            }
#pragma unroll
            for (int mi = 0; mi < 2; mi++)
#pragma unroll
                for (int ni = 0; ni < 8; ni++)
                    mma_tf32(c[mi][ni], af[mi], bf[ni]);
        }
        __syncthreads();
    }

#pragma unroll
    for (int mi = 0; mi < 2; mi++) {
#pragma unroll
        for (int rr = 0; rr < 2; rr++) {
            const int m = m0 + wm + mi * 16 + g + rr * 8;
            const int b_ = m >> 11, s = m & 2047;
#pragma unroll
            for (int ni = 0; ni < 8; ni++) {
                const int n = n0 + wn + ni * 8 + 2 * t;
                float v0 = c[mi][ni][rr * 2 + 0] + bias[n];
                float v1 = c[mi][ni][rr * 2 + 1] + bias[n + 1];
                if (mode == 0) {
                    *(float2*)&out[(size_t)m * 1024 + n] = make_float2(v0, v1);
                } else {
                    v0 = __uint_as_float(f2tf32(v0));
                    v1 = __uint_as_float(f2tf32(v1));
                    const int h = n >> 6, d = n & 63;
                    if (mode == 1) {
                        *(float2*)&out[(((size_t)(b_ * 16 + h) * 2048 + s) << 6) + d] =
                            make_float2(v0, v1);
                    } else {
                        out[((size_t)(b_ * 16 + h) * 64 + d) * 2048 + s] = v0;
                        out[((size_t)(b_ * 16 + h) * 64 + d + 1) * 2048 + s] = v1;
                    }
                }
            }
        }
    }
}

// ---------------------------------------------------------------------------
// Fused attention v2.  CTA = 128 q-rows x (b,h). Warp = 16 rows x 64 keys.
// Q resident in smem.  Mask from bitmask.  PV a-frags via shuffles.
// ---------------------------------------------------------------------------
#define CK 64
#define NCH (SSEQ/CK)         // 32
#define KW 68
#define SM_Q  0               // 128*68   = 8704 words
#define SM_K0 8704            // 64*68    = 4352
#define SM_K1 13056
#define SM_V0 17408
#define SM_V1 21760
#define FA_SMEM_WORDS 26112
#define FA_SMEM_BYTES (FA_SMEM_WORDS*4)   // 104448

__global__ void __launch_bounds__(256, 2) fused_attn(float* __restrict__ P)
{
    extern __shared__ uint32_t sm[];
    const int tid = threadIdx.x;
    const int lane = tid & 31, warp = tid >> 5;
    const int g = lane >> 2, t = lane & 3;
    const int bh = blockIdx.y;
    const int i0 = blockIdx.x * 128;
    const int b_ = bh >> 4, h = bh & 15;
    const int wm = warp * 16;

    const float* Qg = g_q + (size_t)bh * SSEQ * DK;
    const float* Kg = g_k + (size_t)bh * SSEQ * DK;
    const float* Vg = g_vT + (size_t)bh * DK * SSEQ;
    float* Pg = P + (size_t)bh * SSEQ * SSEQ;
    const int row0 = i0 + wm + g;              // this thread's first row
    const uint32_t* mb0 = g_mbits + ((size_t)b_ * SSEQ + row0) * 64;
    const uint32_t* mb1 = mb0 + (size_t)8 * 64;

    const uint32_t sbase = (uint32_t)__cvta_generic_to_shared(sm);

    auto stageK = [&](int c) {
        const uint32_t dbase = sbase + ((c & 1) ? SM_K1 : SM_K0) * 4;
        const float* src = Kg + (size_t)c * CK * DK;
#pragma unroll
        for (int s = 0; s < 4; s++) {
            const int idx = tid + s * 256;
            const int key = idx >> 4, q = idx & 15;
            cp16(dbase + (uint32_t)(key * KW + q * 4) * 4, src + key * DK + q * 4);
        }
    };
    auto stageV = [&](int c) {
        const uint32_t dbase = sbase + ((c & 1) ? SM_V1 : SM_V0) * 4;
#pragma unroll
        for (int s = 0; s < 4; s++) {
            const int idx = tid + s * 256;
            const int d = idx >> 4, q = idx & 15;
            cp16(dbase + (uint32_t)(d * KW + q * 4) * 4,
                 Vg + (size_t)d * SSEQ + c * CK + q * 4);
        }
    };

    // ---- stage Q once (128 x 64) ----
    {
#pragma unroll
        for (int s = 0; s < 8; s++) {
            const int idx = tid + s * 256;
            const int r = idx >> 4, q = idx & 15;
            cp16(sbase + (uint32_t)(SM_Q + r * KW + q * 4) * 4,
                 Qg + (size_t)(i0 + r) * DK + q * 4);
        }
        cp_commit();
    }

    const uint32_t* Qs = sm + SM_Q + (size_t)(wm + g) * KW;   // rows g / g+8 of warp

    // QK^T: 16 rows x 64 keys, Q from smem, K from chunk buffer
    auto qk = [&](const uint32_t* Kb, float cc[8][4]) {
#pragma unroll
        for (int ks = 0; ks < 8; ks++) {
            uint32_t a[4];
            a[0] = Qs[ks * 8 + t];
            a[1] = Qs[8 * KW + ks * 8 + t];
            a[2] = Qs[ks * 8 + t + 4];
            a[3] = Qs[8 * KW + ks * 8 + t + 4];
#pragma unroll
            for (int nt = 0; nt < 8; nt++) {
                uint32_t bb[2] = { Kb[(nt * 8 + g) * KW + ks * 8 + t],
                                   Kb[(nt * 8 + g) * KW + ks * 8 + t + 4] };
                mma_tf32(cc[nt], a, bb);
            }
        }
    };

    // ================= PASS A: row sums =================
    float l0 = 0.f, l1 = 0.f;
    stageK(0); cp_commit();
    for (int c = 0; c < NCH; c++) {
        if (c + 1 < NCH) { stageK(c + 1); cp_commit(); cp_wait<1>(); }
        else             { cp_wait<0>(); }
        __syncthreads();
        const uint32_t* Kb = sm + ((c & 1) ? SM_K1 : SM_K0);
        float cc[8][4] = {};
        qk(Kb, cc);
        const uint2 w0 = *(const uint2*)(mb0 + c * 2);
        const uint2 w1 = *(const uint2*)(mb1 + c * 2);
#pragma unroll
        for (int nt = 0; nt < 8; nt++) {
            const int sh = (nt * 8) & 31;      // + 2t below
            const uint32_t m0w = (nt < 4) ? w0.x : w0.y;
            const uint32_t m1w = (nt < 4) ? w1.x : w1.y;
            l0 += ((m0w >> (sh + 2 * t))     & 1) ? 0.f : __expf(cc[nt][0] * 0.125f);
            l0 += ((m0w >> (sh + 2 * t + 1)) & 1) ? 0.f : __expf(cc[nt][1] * 0.125f);
            l1 += ((m1w >> (sh + 2 * t))     & 1) ? 0.f : __expf(cc[nt][2] * 0.125f);
            l1 += ((m1w >> (sh + 2 * t + 1)) & 1) ? 0.f : __expf(cc[nt][3] * 0.125f);
        }
        __syncthreads();
    }
    l0 += __shfl_xor_sync(0xffffffffu, l0, 1);
    l0 += __shfl_xor_sync(0xffffffffu, l0, 2);
    l1 += __shfl_xor_sync(0xffffffffu, l1, 1);
    l1 += __shfl_xor_sync(0xffffffffu, l1, 2);
    const float inv0 = 1.f / l0, inv1 = 1.f / l1;

    // ================= PASS B: normalize + write P + PV =================
    float oacc[8][4] = {};
    stageK(0); stageV(0); cp_commit();
    for (int c = 0; c < NCH; c++) {
        if (c + 1 < NCH) { stageK(c + 1); stageV(c + 1); cp_commit(); cp_wait<1>(); }
        else             { cp_wait<0>(); }
        __syncthreads();
        const uint32_t* Kb = sm + ((c & 1) ? SM_K1 : SM_K0);
        const uint32_t* Vb = sm + ((c & 1) ? SM_V1 : SM_V0);
        float cc[8][4] = {};
        qk(Kb, cc);
        const int jc = c * CK;
        const uint2 w0 = *(const uint2*)(mb0 + c * 2);
        const uint2 w1 = *(const uint2*)(mb1 + c * 2);
#pragma unroll
        for (int nt = 0; nt < 8; nt++) {
            const int sh = (nt * 8) & 31;
            const uint32_t m0w = (nt < 4) ? w0.x : w0.y;
            const uint32_t m1w = (nt < 4) ? w1.x : w1.y;
            cc[nt][0] = ((m0w >> (sh + 2 * t))     & 1) ? 0.f : __expf(cc[nt][0] * 0.125f) * inv0;
            cc[nt][1] = ((m0w >> (sh + 2 * t + 1)) & 1) ? 0.f : __expf(cc[nt][1] * 0.125f) * inv0;
            cc[nt][2] = ((m1w >> (sh + 2 * t))     & 1) ? 0.f : __expf(cc[nt][2] * 0.125f) * inv1;
            cc[nt][3] = ((m1w >> (sh + 2 * t + 1)) & 1) ? 0.f : __expf(cc[nt][3] * 0.125f) * inv1;
            // store normalized P directly from fragments
            *(float2*)&Pg[(size_t)row0 * SSEQ + jc + nt * 8 + 2 * t] =
                make_float2(cc[nt][0], cc[nt][1]);
            *(float2*)&Pg[(size_t)(row0 + 8) * SSEQ + jc + nt * 8 + 2 * t] =
                make_float2(cc[nt][2], cc[nt][3]);
        }
        // PV: build a-frags from cc via shuffles.  P[row][ks*8+c'] with c'=t (+4)
        const int base = lane & 28;                 // g*4
        const int srcl  = base + (t >> 1);
        const int srcl2 = srcl + 2;
#pragma unroll
        for (int ks = 0; ks < 8; ks++) {
            const float s00 = __shfl_sync(0xffffffffu, cc[ks][0], srcl);
            const float s01 = __shfl_sync(0xffffffffu, cc[ks][1], srcl);
            const float s10 = __shfl_sync(0xffffffffu, cc[ks][2], srcl);
            const float s11 = __shfl_sync(0xffffffffu, cc[ks][3], srcl);
            const float s20 = __shfl_sync(0xffffffffu, cc[ks][0], srcl2);
            const float s21 = __shfl_sync(0xffffffffu, cc[ks][1], srcl2);
            const float s30 = __shfl_sync(0xffffffffu, cc[ks][2], srcl2);
            const float s31 = __shfl_sync(0xffffffffu, cc[ks][3], srcl2);
            uint32_t a[4];
            a[0] = f2tf32((t & 1) ? s01 : s00);
            a[1] = f2tf32((t & 1) ? s11 : s10);
            a[2] = f2tf32((t & 1) ? s21 : s20);
            a[3] = f2tf32((t & 1) ? s31 : s30);
#pragma unroll
            for (int nt = 0; nt < 8; nt++) {
                uint32_t bb[2] = { Vb[(nt * 8 + g) * KW + ks * 8 + t],
                                   Vb[(nt * 8 + g) * KW + ks * 8 + t + 4] };
                mma_tf32(oacc[nt], a, bb);
            }
        }
        __syncthreads();
    }

    // epilogue: merged attn [B,S,H*64]
#pragma unroll
    for (int nt = 0; nt < 8; nt++) {
        const int d = h * 64 + nt * 8 + 2 * t;
        *(float2*)&g_attn[(size_t)(b_ * SSEQ + row0) * DM + d] =
            make_float2(oacc[nt][0], oacc[nt][1]);
        *(float2*)&g_attn[(size_t)(b_ * SSEQ + row0 + 8) * DM + d] =
            make_float2(oacc[nt][2], oacc[nt][3]);
    }
}

// ---------------------------------------------------------------------------
extern "C" void kernel_launch(void* const* d_in, const int* in_sizes, int n_in,
                              void* d_out, int out_size)
{
    const float* Q   = (const float*)d_in[0];
    const float* K   = (const float*)d_in[1];
    const float* V   = (const float*)d_in[2];
    const unsigned char* mask = (const unsigned char*)d_in[3];
    const float* WQw = (const float*)d_in[4];
    const float* WQb = (const float*)d_in[5];
    const float* WKw = (const float*)d_in[6];
    const float* WKb = (const float*)d_in[7];
    const float* WVw = (const float*)d_in[8];
    const float* WVb = (const float*)d_in[9];
    const float* Wow = (const float*)d_in[10];
    const float* Wob = (const float*)d_in[11];

    float* out   = (float*)d_out;                       // [B,S,D]
    float* attnw = out + (size_t)MTOT * DM;             // [B,H,S,S]

    float *pq, *pk, *pv, *pa;
    cudaGetSymbolAddress((void**)&pq, g_q);
    cudaGetSymbolAddress((void**)&pk, g_k);
    cudaGetSymbolAddress((void**)&pv, g_vT);
    cudaGetSymbolAddress((void**)&pa, g_attn);

    cudaFuncSetAttribute(fused_attn, cudaFuncAttributeMaxDynamicSharedMemorySize,
                         FA_SMEM_BYTES);

    maskbits_kernel<<<(BB * SSEQ * (SSEQ / 32)) / 256, 256>>>(mask);

    proj_tf32<<<dim3(8, 32), 256>>>(Q, WQw, WQb, pq, 1);
    proj_tf32<<<dim3(8, 32), 256>>>(K, WKw, WKb, pk, 1);
    proj_tf32<<<dim3(8, 32), 256>>>(V, WVw, WVb, pv, 2);

    fused_attn<<<dim3(16, 32), 256, FA_SMEM_BYTES>>>(attnw);

    proj_tf32<<<dim3(8, 32), 256>>>(pa, Wow, Wob, out, 0);
}